// round 12
// baseline (speedup 1.0000x reference)
#include <cuda_runtime.h>
#include <cuda_fp16.h>
#include <math.h>
#include <cstdint>

// ---------------------------------------------------------------- constants
#define NBLK  16
#define LSEQ  2048
#define CKD   32
#define CVD   64
#define NPOSF 32768.0f
#define EPSB  1e-5f
#define SCALE_Q 0.25505654350925196f   // (1/sqrt(32)) * log2(e)
#define NBANK 32

// per-(nb,kt) staged tile blob: [K fp16 10240 | V fp16 17408]
#define TILE_BYTES 27648
#define BLOB_V     10240

// ---------------------------------------------------------------- scratch
__device__ float g_q [NBLK * LSEQ * CKD];
__device__ float g_k [NBLK * LSEQ * CKD];
__device__ __half g_qh[NBLK * LSEQ * CKD];
__device__ __align__(128) unsigned char g_tiles[NBLK * 16 * TILE_BYTES];
__device__ float g_sum[NBANK * 64], g_sq[NBANK * 64];  // zero at load; attn re-zeroes
__device__ float g_affa[64], g_affc[64];

// ---------------------------------------------------------------- helpers
__device__ __forceinline__ void mma_f16(float* c, const uint32_t* a,
                                        uint32_t b0, uint32_t b1) {
    asm volatile(
        "mma.sync.aligned.m16n8k16.row.col.f32.f16.f16.f32 "
        "{%0,%1,%2,%3}, {%4,%5,%6,%7}, {%8,%9}, {%0,%1,%2,%3};"
        : "+f"(c[0]), "+f"(c[1]), "+f"(c[2]), "+f"(c[3])
        : "r"(a[0]), "r"(a[1]), "r"(a[2]), "r"(a[3]), "r"(b0), "r"(b1));
}
__device__ __forceinline__ uint32_t pack_f16x2(float lo, float hi) {
    uint32_t r;
    asm("cvt.rn.f16x2.f32 %0, %1, %2;" : "=r"(r) : "f"(hi), "f"(lo));
    return r;
}
#define LDSM_X4(r0, r1, r2, r3, addr) \
    asm volatile("ldmatrix.sync.aligned.m8n8.x4.shared.b16 {%0,%1,%2,%3}, [%4];" \
        : "=r"(r0), "=r"(r1), "=r"(r2), "=r"(r3) : "r"(addr))

#define MBARRIER_INIT(mb, cnt) \
    asm volatile("mbarrier.init.shared.b64 [%0], %1;" :: "r"((uint32_t)(mb)), "r"((uint32_t)(cnt)) : "memory")
#define MBARRIER_EXPECT_TX(mb, bytes) \
    asm volatile("mbarrier.arrive.expect_tx.shared.b64 _, [%0], %1;" :: "r"((uint32_t)(mb)), "r"((uint32_t)(bytes)) : "memory")
#define CP_BULK(dst, src, bytes, mbar) \
    asm volatile("cp.async.bulk.shared::cta.global.mbarrier::complete_tx::bytes [%0], [%1], %2, [%3];" \
                 :: "r"((uint32_t)(dst)), "l"(src), "r"((uint32_t)(bytes)), "r"((uint32_t)(mbar)) : "memory")
#define MBARRIER_WAIT_PARITY(mb, par) do {                                          \
    uint32_t _mbar = (uint32_t)(mb); uint32_t _par = (uint32_t)(par); uint32_t _done;\
    asm volatile("{\n\t.reg .pred p;\n\t"                                           \
        "mbarrier.try_wait.parity.acquire.cta.shared::cta.b64 p, [%1], %2;\n\t"     \
        "selp.b32 %0, 1, 0, p;\n\t}" : "=r"(_done) : "r"(_mbar), "r"(_par) : "memory"); \
    if (!_done) {                                                                   \
        asm volatile("{\n\t.reg .pred P1;\n\t"                                      \
            "WAIT_LOOP_%=:\n\t"                                                     \
            "mbarrier.try_wait.parity.acquire.cta.shared::cta.b64 P1, [%0], %1, 0x989680;\n\t" \
            "@P1 bra.uni WAIT_DONE_%=;\n\t"                                         \
            "bra.uni WAIT_LOOP_%=;\n\t"                                             \
            "WAIT_DONE_%=:\n\t}" :: "r"(_mbar), "r"(_par) : "memory");              \
    } } while (0)

__device__ __forceinline__ uint32_t smem_u32(const void* p) {
    uint32_t a;
    asm("{ .reg .u64 t; cvta.to.shared.u64 t, %1; cvt.u32.u64 %0, t; }" : "=r"(a) : "l"(p));
    return a;
}

// ---------------------------------------------------------------- kernel 1: conv1x1
// CTA = (n, h, w0): 16 w-positions x 2 sides -> 32 consecutive l per (nb,kt)
__global__ __launch_bounds__(128) void conv_kernel(
    const float* __restrict__ x,
    const float* __restrict__ Wq, const float* __restrict__ bq,
    const float* __restrict__ Wk, const float* __restrict__ bk,
    const float* __restrict__ Wv, const float* __restrict__ bv)
{
    __shared__ float xs[64 * 32];
    __shared__ float wsm[128 * 65];
    const int tid = threadIdx.x;
    const int bid = blockIdx.x;
    const int n   = bid >> 8;
    const int rem = bid & 255;
    const int h   = rem >> 2;
    const int w0  = (rem & 3) * 16;

    const float* xbase = x + (size_t)n * 64 * 8192 + h * 128;
    for (int f = tid; f < 64 * 32; f += 128) {
        int c = f >> 5, pos = f & 31;
        int w2 = ((pos >> 4) << 6) + w0 + (pos & 15);
        xs[c * 32 + pos] = xbase[c * 8192 + w2];
    }
    for (int f = tid; f < 128 * 64; f += 128) {
        int o = f >> 6, c = f & 63;
        float w;
        if      (o < 32) w = Wq[o * 64 + c];
        else if (o < 64) w = Wk[(o - 32) * 64 + c];
        else             w = Wv[(o - 64) * 64 + c];
        wsm[o * 65 + c] = w;
    }
    __syncthreads();

    const int oc = tid;
    float bias;
    if      (oc < 32) bias = bq[oc];
    else if (oc < 64) bias = bk[oc - 32];
    else              bias = bv[oc - 64];

    float acc[32];
#pragma unroll
    for (int p = 0; p < 32; p++) acc[p] = bias;

    const float4* xs4 = (const float4*)xs;
#pragma unroll 8
    for (int c = 0; c < 64; c++) {
        float wv = wsm[oc * 65 + c];
#pragma unroll
        for (int p4 = 0; p4 < 8; p4++) {
            float4 xv = xs4[c * 8 + p4];
            acc[p4 * 4 + 0] += wv * xv.x;
            acc[p4 * 4 + 1] += wv * xv.y;
            acc[p4 * 4 + 2] += wv * xv.z;
            acc[p4 * 4 + 3] += wv * xv.w;
        }
    }

    const int b    = ((h >> 5) << 1) | (w0 >> 5);
    const int nb   = (n << 2) | b;
    const int l0   = ((h & 31) * 32 + (w0 & 31)) * 2;   // 32 consecutive l from l0
    const int kt   = l0 >> 7;
    const int key0 = l0 & 127;

    if (oc < 64) {
        float s = 0.f, sq = 0.f;
#pragma unroll
        for (int p = 0; p < 32; p++) {
            int l = l0 + ((p & 15) << 1) + (p >> 4);
            float v = acc[p];
            if (oc < 32) g_q[(size_t)(nb * LSEQ + l) * CKD + oc]        = v;
            else         g_k[(size_t)(nb * LSEQ + l) * CKD + (oc - 32)] = v;
            s += v; sq += v * v;
        }
        const int bank = (bid & (NBANK - 1)) * 64 + oc;
        atomicAdd(&g_sum[bank], s);
        atomicAdd(&g_sq[bank],  sq);
    } else {
        // V: fp16, straight into the tile blob (contiguous 64B per channel)
        const int cv = oc - 64;
        uint32_t pk[16];
#pragma unroll
        for (int p = 0; p < 16; p++) pk[p] = pack_f16x2(acc[p], acc[p + 16]);
        unsigned char* dst = g_tiles + (size_t)(nb * 16 + kt) * TILE_BYTES
                             + BLOB_V + cv * 272 + key0 * 2;
#pragma unroll
        for (int j = 0; j < 4; j++)
            *(uint4*)(dst + j * 16) =
                make_uint4(pk[4*j], pk[4*j+1], pk[4*j+2], pk[4*j+3]);
    }
}

// ---------------------------------------------------------------- kernel 2: BN fold (banked reduce)
__global__ void bn_kernel(const float* __restrict__ gq, const float* __restrict__ betaq,
                          const float* __restrict__ gk, const float* __restrict__ betak)
{
    int c = threadIdx.x;  // 0..63
    float s = 0.f, sq = 0.f;
#pragma unroll
    for (int b = 0; b < NBANK; b++) {
        s  += g_sum[b * 64 + c];
        sq += g_sq [b * 64 + c];
    }
    float mean = s / NPOSF;
    float var  = sq / NPOSF - mean * mean;
    float gg   = (c < 32) ? gq[c]    : gk[c - 32];
    float be   = (c < 32) ? betaq[c] : betak[c - 32];
    float a    = gg * rsqrtf(var + EPSB);
    g_affa[c] = a;
    g_affc[c] = be - mean * a;
}

// ---------------------------------------------------------------- kernel 3: prep (q/k only, fp16)
__global__ __launch_bounds__(256) void prep_kernel() {
    int idx = blockIdx.x * 256 + threadIdx.x;       // 0 .. 1M-1 (pairs)
    int which = idx >> 19;                          // 0: q, 1: k
    int i = (idx & 524287) * 2;
    int ck = i & 31;
    const float* src = which ? g_k : g_q;
    float2 rv = *(const float2*)(src + i);
    int base = which ? 32 : 0;
    float a0 = g_affa[base + ck],     c0 = g_affc[base + ck];
    float a1 = g_affa[base + ck + 1], c1 = g_affc[base + ck + 1];
    float y0 = rv.x * a0 + c0;
    float y1 = rv.y * a1 + c1;
    if (!which) { y0 *= SCALE_Q; y1 *= SCALE_Q; }
    uint32_t hw = pack_f16x2(y0, y1);
    if (which) {
        int nb  = i >> 16;
        int rem = i & 65535;
        int l   = rem >> 5;
        int kt  = l >> 7, row = l & 127;
        *(uint32_t*)(g_tiles + (size_t)(nb * 16 + kt) * TILE_BYTES + row * 80 + ck * 2) = hw;
    } else {
        ((uint32_t*)g_qh)[i >> 1] = hw;
    }
}

// ---------------------------------------------------------------- attention
// 128 threads, 4 warps; warp w owns rows w*32..w*32+31 (two m16 tiles), all 128 keys.
// smem byte layout:
//  buf b (b=0,1) at b*27648: K fp16 +0 (pitch 80) | V fp16 +10240 (pitch 272)
//  Q:   55296 (fp16, pitch 80, 10240 B)
//  mbar:65536 (2 x 8B)
#define OFF_Q    55296
#define OFF_MBAR 65536
#define SMEM_BYTES 65792
#define STG_PITCH 66       // float staging overlays offset 0 at the end

extern __shared__ char s_raw[];

__global__ __launch_bounds__(128) void attn_kernel(float* __restrict__ out)
{
    const uint32_t sb = smem_u32(s_raw);
    float* stg = (float*)s_raw;

    const int tid = threadIdx.x;
    const int w   = tid >> 5;      // warp: rows w*32 .. +31
    const int ln  = tid & 31;
    const int qr  = ln >> 2;
    const int qc  = ln & 3;
    const int nb    = blockIdx.y;
    const int chunk = blockIdx.x;
    const int qbase = chunk * 128;

    const int li   = ln & 7;
    const int tsel = ln >> 3;

    const uint32_t kbase = (uint32_t)(((tsel >> 1) * 8 + li) * 80 + (tsel & 1) * 16);
    const uint32_t vbase = (uint32_t)(((tsel >> 1) * 8 + li) * 272 + ((tsel & 1) * 8) * 2);
    // Q fragment bases for the two m16 tiles
    const uint32_t qfrag0 = (uint32_t)((w * 32 + (tsel & 1) * 8 + li) * 80 + (tsel >> 1) * 16);
    const uint32_t qfrag1 = qfrag0 + 16 * 80;

    const unsigned char* tiles = g_tiles + (size_t)nb * 16 * TILE_BYTES;

    // ---- init mbarriers, kick tile-0 bulk copy, stage Q ----
    if (tid == 0) {
        MBARRIER_INIT(sb + OFF_MBAR,     1);
        MBARRIER_INIT(sb + OFF_MBAR + 8, 1);
    }
    __syncthreads();
    if (tid == 0) {
        MBARRIER_EXPECT_TX(sb + OFF_MBAR, TILE_BYTES);
        CP_BULK(sb, tiles, TILE_BYTES, sb + OFF_MBAR);
    }
    for (int f = tid; f < 512; f += 128) {
        int row = f >> 2, j = f & 3;
        const size_t src = ((size_t)(nb * LSEQ + qbase + row)) * CKD + j * 8;
        *(uint4*)(s_raw + OFF_Q + row * 80 + j * 16) = *(const uint4*)(g_qh + src);
    }
    __syncthreads();

    // ---- hoist Q fragments (two m-tiles) ----
    uint32_t Qh[2][2][4];
#pragma unroll
    for (int s = 0; s < 2; s++) {
        LDSM_X4(Qh[0][s][0], Qh[0][s][1], Qh[0][s][2], Qh[0][s][3],
                sb + OFF_Q + s * 32 + qfrag0);
        LDSM_X4(Qh[1][s][0], Qh[1][s][1], Qh[1][s][2], Qh[1][s][3],
                sb + OFF_Q + s * 32 + qfrag1);
    }

    float O[2][8][4];
#pragma unroll
    for (int m = 0; m < 2; m++)
#pragma unroll
        for (int v = 0; v < 8; v++)
#pragma unroll
            for (int j = 0; j < 4; j++) O[m][v][j] = 0.f;
    float rs[2][2] = {{0.f, 0.f}, {0.f, 0.f}};

    for (int kt = 0; kt < 16; kt++) {
        MBARRIER_WAIT_PARITY(sb + OFF_MBAR + (kt & 1) * 8, (kt >> 1) & 1);
        __syncthreads();
        if (tid == 0 && kt < 15) {
            const uint32_t mbn = sb + OFF_MBAR + ((kt + 1) & 1) * 8;
            MBARRIER_EXPECT_TX(mbn, TILE_BYTES);
            CP_BULK(sb + ((kt + 1) & 1) * TILE_BYTES,
                    tiles + (size_t)(kt + 1) * TILE_BYTES, TILE_BYTES, mbn);
        }

        const uint32_t kB = sb + (kt & 1) * TILE_BYTES;
        const uint32_t vB = kB + BLOB_V;

        // ---- fused per key-pair (16 keys): S mma -> exp2 -> fp16 pack -> PV mma ----
#pragma unroll
        for (int t = 0; t < 8; t++) {
            float P[2][2][4];
#pragma unroll
            for (int m = 0; m < 2; m++)
#pragma unroll
                for (int u = 0; u < 2; u++)
#pragma unroll
                    for (int j = 0; j < 4; j++) P[m][u][j] = 0.f;

#pragma unroll
            for (int s = 0; s < 2; s++) {
                uint32_t kh[4];
                LDSM_X4(kh[0], kh[1], kh[2], kh[3], kB + t * 1280 + s * 32 + kbase);
                mma_f16(P[0][0], Qh[0][s], kh[0], kh[1]);
                mma_f16(P[0][1], Qh[0][s], kh[2], kh[3]);
                mma_f16(P[1][0], Qh[1][s], kh[0], kh[1]);
                mma_f16(P[1][1], Qh[1][s], kh[2], kh[3]);
            }

            uint32_t A[2][4];
#pragma unroll
            for (int m = 0; m < 2; m++) {
#pragma unroll
                for (int u = 0; u < 2; u++)
#pragma unroll
                    for (int j = 0; j < 4; j++) P[m][u][j] = exp2f(P[m][u][j]);
                rs[m][0] += P[m][0][0] + P[m][0][1] + P[m][1][0] + P[m][1][1];
                rs[m][1] += P[m][0][2] + P[m][0][3] + P[m][1][2] + P[m][1][3];
                A[m][0] = pack_f16x2(P[m][0][0], P[m][0][1]);
                A[m][1] = pack_f16x2(P[m][0][2], P[m][0][3]);
                A[m][2] = pack_f16x2(P[m][1][0], P[m][1][1]);
                A[m][3] = pack_f16x2(P[m][1][2], P[m][1][3]);
            }

#pragma unroll
            for (int i = 0; i < 4; i++) {
                const int vp = 2 * i;
                uint32_t vh[4];
                LDSM_X4(vh[0], vh[1], vh[2], vh[3], vB + vp * 2176 + t * 32 + vbase);
                mma_f16(O[0][vp],     A[0], vh[0], vh[1]);
                mma_f16(O[0][vp + 1], A[0], vh[2], vh[3]);
                mma_f16(O[1][vp],     A[1], vh[0], vh[1]);
                mma_f16(O[1][vp + 1], A[1], vh[2], vh[3]);
            }
        }
    }

    // ---- normalize in-register, stage, scatter ----
#pragma unroll
    for (int m = 0; m < 2; m++)
#pragma unroll
        for (int u = 0; u < 2; u++) {
            rs[m][u] += __shfl_xor_sync(0xffffffffu, rs[m][u], 1);
            rs[m][u] += __shfl_xor_sync(0xffffffffu, rs[m][u], 2);
        }

    __syncthreads();   // all smem-tile reads done; stg overlay safe
#pragma unroll
    for (int m = 0; m < 2; m++) {
        const float inv0 = 1.0f / rs[m][0];
        const float inv1 = 1.0f / rs[m][1];
        const int r0 = w * 32 + m * 16 + qr;
#pragma unroll
        for (int v = 0; v < 8; v++) {
            int cv = v * 8 + qc * 2;
            *(float2*)&stg[(r0)     * STG_PITCH + cv] =
                make_float2(O[m][v][0] * inv0, O[m][v][1] * inv0);
            *(float2*)&stg[(r0 + 8) * STG_PITCH + cv] =
                make_float2(O[m][v][2] * inv1, O[m][v][3] * inv1);
        }
    }
    __syncthreads();

    const int n = nb >> 2, b = nb & 3;
    const int bi = b >> 1, bj = b & 1;
    for (int e = tid; e < 8192; e += 128) {
        int wl   = e & 31;
        int side = (e >> 5) & 1;
        int hlo  = (e >> 6) & 1;
        int cv   = e >> 7;
        int ll   = hlo * 64 + wl * 2 + side;
        int hh   = bi * 32 + chunk * 2 + hlo;
        int w2   = side * 64 + bj * 32 + wl;
        out[(((size_t)(n * 64 + cv)) * 64 + hh) * 128 + w2] = stg[ll * STG_PITCH + cv];
    }

    // re-zero banked BN stat accumulators for the next launch
    if (blockIdx.x == 0 && blockIdx.y == 0) {
        for (int i = tid; i < NBANK * 64; i += 128) {
            g_sum[i] = 0.f;
            g_sq[i]  = 0.f;
        }
    }
}

// ---------------------------------------------------------------- launch
extern "C" void kernel_launch(void* const* d_in, const int* in_sizes, int n_in,
                              void* d_out, int out_size)
{
    (void)in_sizes; (void)n_in; (void)out_size;
    const float* x     = (const float*)d_in[0];
    const float* Wq    = (const float*)d_in[1];
    const float* bq    = (const float*)d_in[2];
    const float* gq    = (const float*)d_in[3];
    const float* betaq = (const float*)d_in[4];
    const float* Wk    = (const float*)d_in[5];
    const float* bk    = (const float*)d_in[6];
    const float* gk    = (const float*)d_in[7];
    const float* betak = (const float*)d_in[8];
    const float* Wv    = (const float*)d_in[9];
    const float* bv    = (const float*)d_in[10];
    float* out = (float*)d_out;

    cudaFuncSetAttribute(attn_kernel, cudaFuncAttributeMaxDynamicSharedMemorySize,
                         SMEM_BYTES);

    conv_kernel<<<1024, 128>>>(x, Wq, bq, Wk, bk, Wv, bv);
    bn_kernel<<<1, 64>>>(gq, betaq, gk, betak);
    prep_kernel<<<4096, 256>>>();
    attn_kernel<<<dim3(16, 16), 128, SMEM_BYTES>>>(out);
}

// round 13
// speedup vs baseline: 1.2384x; 1.2384x over previous
#include <cuda_runtime.h>
#include <cuda_fp16.h>
#include <math.h>
#include <cstdint>

// ---------------------------------------------------------------- constants
#define NBLK  16
#define LSEQ  2048
#define CKD   32
#define CVD   64
#define NPOSF 32768.0f
#define EPSB  1e-5f
#define SCALE_Q 0.25505654350925196f   // (1/sqrt(32)) * log2(e)
#define NBANK 32

// per-(nb,kt) staged tile blob: [K fp16 10240 | V fp16 17408]
#define TILE_BYTES 27648
#define BLOB_V     10240

// ---------------------------------------------------------------- scratch
__device__ float g_q [NBLK * LSEQ * CKD];
__device__ float g_k [NBLK * LSEQ * CKD];
__device__ __half g_qh[NBLK * LSEQ * CKD];
__device__ __align__(128) unsigned char g_tiles[NBLK * 16 * TILE_BYTES];
__device__ float g_sum[NBANK * 64], g_sq[NBANK * 64];  // zero at load; attn re-zeroes
__device__ float g_affa[64], g_affc[64];

// ---------------------------------------------------------------- helpers
__device__ __forceinline__ void mma_f16(float* c, const uint32_t* a,
                                        uint32_t b0, uint32_t b1) {
    asm volatile(
        "mma.sync.aligned.m16n8k16.row.col.f32.f16.f16.f32 "
        "{%0,%1,%2,%3}, {%4,%5,%6,%7}, {%8,%9}, {%0,%1,%2,%3};"
        : "+f"(c[0]), "+f"(c[1]), "+f"(c[2]), "+f"(c[3])
        : "r"(a[0]), "r"(a[1]), "r"(a[2]), "r"(a[3]), "r"(b0), "r"(b1));
}
__device__ __forceinline__ uint32_t pack_f16x2(float lo, float hi) {
    uint32_t r;
    asm("cvt.rn.f16x2.f32 %0, %1, %2;" : "=r"(r) : "f"(hi), "f"(lo));
    return r;
}
#define LDSM_X4(r0, r1, r2, r3, addr) \
    asm volatile("ldmatrix.sync.aligned.m8n8.x4.shared.b16 {%0,%1,%2,%3}, [%4];" \
        : "=r"(r0), "=r"(r1), "=r"(r2), "=r"(r3) : "r"(addr))

#define MBARRIER_INIT(mb, cnt) \
    asm volatile("mbarrier.init.shared.b64 [%0], %1;" :: "r"((uint32_t)(mb)), "r"((uint32_t)(cnt)) : "memory")
#define MBARRIER_EXPECT_TX(mb, bytes) \
    asm volatile("mbarrier.arrive.expect_tx.shared.b64 _, [%0], %1;" :: "r"((uint32_t)(mb)), "r"((uint32_t)(bytes)) : "memory")
#define CP_BULK(dst, src, bytes, mbar) \
    asm volatile("cp.async.bulk.shared::cta.global.mbarrier::complete_tx::bytes [%0], [%1], %2, [%3];" \
                 :: "r"((uint32_t)(dst)), "l"(src), "r"((uint32_t)(bytes)), "r"((uint32_t)(mbar)) : "memory")
#define MBARRIER_WAIT_PARITY(mb, par) do {                                          \
    uint32_t _mbar = (uint32_t)(mb); uint32_t _par = (uint32_t)(par); uint32_t _done;\
    asm volatile("{\n\t.reg .pred p;\n\t"                                           \
        "mbarrier.try_wait.parity.acquire.cta.shared::cta.b64 p, [%1], %2;\n\t"     \
        "selp.b32 %0, 1, 0, p;\n\t}" : "=r"(_done) : "r"(_mbar), "r"(_par) : "memory"); \
    if (!_done) {                                                                   \
        asm volatile("{\n\t.reg .pred P1;\n\t"                                      \
            "WAIT_LOOP_%=:\n\t"                                                     \
            "mbarrier.try_wait.parity.acquire.cta.shared::cta.b64 P1, [%0], %1, 0x989680;\n\t" \
            "@P1 bra.uni WAIT_DONE_%=;\n\t"                                         \
            "bra.uni WAIT_LOOP_%=;\n\t"                                             \
            "WAIT_DONE_%=:\n\t}" :: "r"(_mbar), "r"(_par) : "memory");              \
    } } while (0)

__device__ __forceinline__ uint32_t smem_u32(const void* p) {
    uint32_t a;
    asm("{ .reg .u64 t; cvta.to.shared.u64 t, %1; cvt.u32.u64 %0, t; }" : "=r"(a) : "l"(p));
    return a;
}

// ---------------------------------------------------------------- kernel 1: conv1x1
// CTA = (n, h, w0): 16 w-positions x 2 sides = 32 consecutive l per (nb,kt).
// 256 threads = 128 oc x 2 pixel-halves (ph): thread owns 8 w-positions x 2 sides.
__global__ __launch_bounds__(256) void conv_kernel(
    const float* __restrict__ x,
    const float* __restrict__ Wq, const float* __restrict__ bq,
    const float* __restrict__ Wk, const float* __restrict__ bk,
    const float* __restrict__ Wv, const float* __restrict__ bv)
{
    __shared__ float xs[64 * 32];
    __shared__ float wsm[128 * 65];
    const int tid = threadIdx.x;
    const int bid = blockIdx.x;
    const int n   = bid >> 8;
    const int rem = bid & 255;
    const int h   = rem >> 2;
    const int w0  = (rem & 3) * 16;

    const float* xbase = x + (size_t)n * 64 * 8192 + h * 128;
    for (int f = tid; f < 64 * 32; f += 256) {
        int c = f >> 5, pos = f & 31;
        int w2 = ((pos >> 4) << 6) + w0 + (pos & 15);
        xs[c * 32 + pos] = xbase[c * 8192 + w2];
    }
    for (int f = tid; f < 128 * 64; f += 256) {
        int o = f >> 6, c = f & 63;
        float w;
        if      (o < 32) w = Wq[o * 64 + c];
        else if (o < 64) w = Wk[(o - 32) * 64 + c];
        else             w = Wv[(o - 64) * 64 + c];
        wsm[o * 65 + c] = w;
    }
    __syncthreads();

    const int oc = tid & 127;
    const int ph = tid >> 7;      // pixel half: w-positions [ph*8, ph*8+8)
    float bias;
    if      (oc < 32) bias = bq[oc];
    else if (oc < 64) bias = bk[oc - 32];
    else              bias = bv[oc - 64];

    // acc[s*8 + j]: side s, w-position ph*8+j
    float acc[16];
#pragma unroll
    for (int p = 0; p < 16; p++) acc[p] = bias;

    const float4* xs4 = (const float4*)xs;
#pragma unroll 8
    for (int c = 0; c < 64; c++) {
        float wv = wsm[oc * 65 + c];
#pragma unroll
        for (int s = 0; s < 2; s++) {
            float4 xa = xs4[c * 8 + s * 4 + ph * 2];
            float4 xb = xs4[c * 8 + s * 4 + ph * 2 + 1];
            acc[s * 8 + 0] += wv * xa.x;
            acc[s * 8 + 1] += wv * xa.y;
            acc[s * 8 + 2] += wv * xa.z;
            acc[s * 8 + 3] += wv * xa.w;
            acc[s * 8 + 4] += wv * xb.x;
            acc[s * 8 + 5] += wv * xb.y;
            acc[s * 8 + 6] += wv * xb.z;
            acc[s * 8 + 7] += wv * xb.w;
        }
    }

    const int b    = ((h >> 5) << 1) | (w0 >> 5);
    const int nb   = (n << 2) | b;
    const int l0   = ((h & 31) * 32 + (w0 & 31)) * 2;   // base l for this CTA
    const int kt   = l0 >> 7;
    const int key0 = l0 & 127;

    if (oc < 64) {
        float s = 0.f, sq = 0.f;
#pragma unroll
        for (int p = 0; p < 16; p++) {
            int side = p >> 3, j = p & 7;
            int l = l0 + ((ph * 8 + j) << 1) + side;
            float v = acc[p];
            if (oc < 32) g_q[(size_t)(nb * LSEQ + l) * CKD + oc]        = v;
            else         g_k[(size_t)(nb * LSEQ + l) * CKD + (oc - 32)] = v;
            s += v; sq += v * v;
        }
        const int bank = (bid & (NBANK - 1)) * 64 + oc;
        atomicAdd(&g_sum[bank], s);
        atomicAdd(&g_sq[bank],  sq);
    } else {
        // V: fp16, straight into the tile blob (contiguous 32B per thread)
        const int cv = oc - 64;
        uint32_t pk[8];
#pragma unroll
        for (int j = 0; j < 8; j++) pk[j] = pack_f16x2(acc[j], acc[8 + j]);
        unsigned char* dst = g_tiles + (size_t)(nb * 16 + kt) * TILE_BYTES
                             + BLOB_V + cv * 272 + (key0 + ph * 16) * 2;
        *(uint4*)(dst)      = make_uint4(pk[0], pk[1], pk[2], pk[3]);
        *(uint4*)(dst + 16) = make_uint4(pk[4], pk[5], pk[6], pk[7]);
    }
}

// ---------------------------------------------------------------- kernel 2: BN fold (banked reduce)
__global__ void bn_kernel(const float* __restrict__ gq, const float* __restrict__ betaq,
                          const float* __restrict__ gk, const float* __restrict__ betak)
{
    int c = threadIdx.x;  // 0..63
    float s = 0.f, sq = 0.f;
#pragma unroll
    for (int b = 0; b < NBANK; b++) {
        s  += g_sum[b * 64 + c];
        sq += g_sq [b * 64 + c];
    }
    float mean = s / NPOSF;
    float var  = sq / NPOSF - mean * mean;
    float gg   = (c < 32) ? gq[c]    : gk[c - 32];
    float be   = (c < 32) ? betaq[c] : betak[c - 32];
    float a    = gg * rsqrtf(var + EPSB);
    g_affa[c] = a;
    g_affc[c] = be - mean * a;
}

// ---------------------------------------------------------------- kernel 3: prep (q/k only, fp16)
__global__ __launch_bounds__(256) void prep_kernel() {
    int idx = blockIdx.x * 256 + threadIdx.x;       // 0 .. 1M-1 (pairs)
    int which = idx >> 19;                          // 0: q, 1: k
    int i = (idx & 524287) * 2;
    int ck = i & 31;
    const float* src = which ? g_k : g_q;
    float2 rv = *(const float2*)(src + i);
    int base = which ? 32 : 0;
    float a0 = g_affa[base + ck],     c0 = g_affc[base + ck];
    float a1 = g_affa[base + ck + 1], c1 = g_affc[base + ck + 1];
    float y0 = rv.x * a0 + c0;
    float y1 = rv.y * a1 + c1;
    if (!which) { y0 *= SCALE_Q; y1 *= SCALE_Q; }
    uint32_t hw = pack_f16x2(y0, y1);
    if (which) {
        int nb  = i >> 16;
        int rem = i & 65535;
        int l   = rem >> 5;
        int kt  = l >> 7, row = l & 127;
        *(uint32_t*)(g_tiles + (size_t)(nb * 16 + kt) * TILE_BYTES + row * 80 + ck * 2) = hw;
    } else {
        ((uint32_t*)g_qh)[i >> 1] = hw;
    }
}

// ---------------------------------------------------------------- attention
// 256 threads, 8 warps; warp w owns rows w*16..w*16+15, all 128 keys. (R11 config)
// smem byte layout:
//  buf b (b=0,1) at b*27648: K fp16 +0 (pitch 80) | V fp16 +10240 (pitch 272)
//  Q:   55296 (fp16, pitch 80, 10240 B)
//  mbar:65536 (2 x 8B)
#define OFF_Q    55296
#define OFF_MBAR 65536
#define SMEM_BYTES 65792
#define STG_PITCH 66       // float staging overlays offset 0 at the end

extern __shared__ char s_raw[];

__global__ __launch_bounds__(256, 2) void attn_kernel(float* __restrict__ out)
{
    const uint32_t sb = smem_u32(s_raw);
    float* stg = (float*)s_raw;

    const int tid = threadIdx.x;
    const int w   = tid >> 5;      // warp = m band: rows w*16 .. +15
    const int ln  = tid & 31;
    const int qr  = ln >> 2;
    const int qc  = ln & 3;
    const int nb    = blockIdx.y;
    const int chunk = blockIdx.x;
    const int qbase = chunk * 128;

    const int li   = ln & 7;
    const int tsel = ln >> 3;

    const uint32_t kbase = (uint32_t)(((tsel >> 1) * 8 + li) * 80 + (tsel & 1) * 16);
    const uint32_t vbase = (uint32_t)(((tsel >> 1) * 8 + li) * 272 + ((tsel & 1) * 8) * 2);
    const uint32_t qfrag = (uint32_t)((w * 16 + (tsel & 1) * 8 + li) * 80 + (tsel >> 1) * 16);

    const unsigned char* tiles = g_tiles + (size_t)nb * 16 * TILE_BYTES;

    // ---- init mbarriers, kick tile-0 bulk copy, stage Q ----
    if (tid == 0) {
        MBARRIER_INIT(sb + OFF_MBAR,     1);
        MBARRIER_INIT(sb + OFF_MBAR + 8, 1);
    }
    __syncthreads();
    if (tid == 0) {
        MBARRIER_EXPECT_TX(sb + OFF_MBAR, TILE_BYTES);
        CP_BULK(sb, tiles, TILE_BYTES, sb + OFF_MBAR);
    }
    for (int f = tid; f < 512; f += 256) {
        int row = f >> 2, j = f & 3;
        const size_t src = ((size_t)(nb * LSEQ + qbase + row)) * CKD + j * 8;
        *(uint4*)(s_raw + OFF_Q + row * 80 + j * 16) = *(const uint4*)(g_qh + src);
    }
    __syncthreads();

    // ---- hoist Q fragments ----
    uint32_t Qh[2][4];
#pragma unroll
    for (int s = 0; s < 2; s++)
        LDSM_X4(Qh[s][0], Qh[s][1], Qh[s][2], Qh[s][3], sb + OFF_Q + s * 32 + qfrag);

    float O[8][4];
#pragma unroll
    for (int v = 0; v < 8; v++)
#pragma unroll
        for (int j = 0; j < 4; j++) O[v][j] = 0.f;
    float rs0 = 0.f, rs1 = 0.f;

    for (int kt = 0; kt < 16; kt++) {
        MBARRIER_WAIT_PARITY(sb + OFF_MBAR + (kt & 1) * 8, (kt >> 1) & 1);
        __syncthreads();
        if (tid == 0 && kt < 15) {
            const uint32_t mbn = sb + OFF_MBAR + ((kt + 1) & 1) * 8;
            MBARRIER_EXPECT_TX(mbn, TILE_BYTES);
            CP_BULK(sb + ((kt + 1) & 1) * TILE_BYTES,
                    tiles + (size_t)(kt + 1) * TILE_BYTES, TILE_BYTES, mbn);
        }

        const uint32_t kB = sb + (kt & 1) * TILE_BYTES;
        const uint32_t vB = kB + BLOB_V;

        // ---- fused per key-pair (16 keys): S mma -> exp2 -> fp16 pack -> PV mma ----
#pragma unroll
        for (int t = 0; t < 8; t++) {
            float P0[4] = {0.f, 0.f, 0.f, 0.f};
            float P1[4] = {0.f, 0.f, 0.f, 0.f};
#pragma unroll
            for (int s = 0; s < 2; s++) {
                uint32_t kh[4];
                LDSM_X4(kh[0], kh[1], kh[2], kh[3], kB + t * 1280 + s * 32 + kbase);
                mma_f16(P0, Qh[s], kh[0], kh[1]);
                mma_f16(P1, Qh[s], kh[2], kh[3]);
            }

#pragma unroll
            for (int j = 0; j < 4; j++) { P0[j] = exp2f(P0[j]); P1[j] = exp2f(P1[j]); }
            rs0 += P0[0] + P0[1] + P1[0] + P1[1];
            rs1 += P0[2] + P0[3] + P1[2] + P1[3];

            uint32_t A[4];
            A[0] = pack_f16x2(P0[0], P0[1]);
            A[1] = pack_f16x2(P0[2], P0[3]);
            A[2] = pack_f16x2(P1[0], P1[1]);
            A[3] = pack_f16x2(P1[2], P1[3]);

#pragma unroll
            for (int i = 0; i < 4; i++) {
                const int vp = 2 * i;
                uint32_t vh[4];
                LDSM_X4(vh[0], vh[1], vh[2], vh[3], vB + vp * 2176 + t * 32 + vbase);
                mma_f16(O[vp],     A, vh[0], vh[1]);
                mma_f16(O[vp + 1], A, vh[2], vh[3]);
            }
        }
    }

    // ---- normalize in-register, stage, scatter ----
    rs0 += __shfl_xor_sync(0xffffffffu, rs0, 1);
    rs0 += __shfl_xor_sync(0xffffffffu, rs0, 2);
    rs1 += __shfl_xor_sync(0xffffffffu, rs1, 1);
    rs1 += __shfl_xor_sync(0xffffffffu, rs1, 2);
    const float inv0 = 1.0f / rs0;
    const float inv1 = 1.0f / rs1;
    const int row0 = w * 16 + qr;

    __syncthreads();   // all smem-tile reads done; stg overlay safe
#pragma unroll
    for (int v = 0; v < 8; v++) {
        int cv = v * 8 + qc * 2;
        *(float2*)&stg[(row0)     * STG_PITCH + cv] =
            make_float2(O[v][0] * inv0, O[v][1] * inv0);
        *(float2*)&stg[(row0 + 8) * STG_PITCH + cv] =
            make_float2(O[v][2] * inv1, O[v][3] * inv1);
    }
    __syncthreads();

    const int n = nb >> 2, b = nb & 3;
    const int bi = b >> 1, bj = b & 1;
    for (int e = tid; e < 8192; e += 256) {
        int wl   = e & 31;
        int side = (e >> 5) & 1;
        int hlo  = (e >> 6) & 1;
        int cv   = e >> 7;
        int ll   = hlo * 64 + wl * 2 + side;
        int hh   = bi * 32 + chunk * 2 + hlo;
        int w2   = side * 64 + bj * 32 + wl;
        out[(((size_t)(n * 64 + cv)) * 64 + hh) * 128 + w2] = stg[ll * STG_PITCH + cv];
    }

    // re-zero banked BN stat accumulators for the next launch
    if (blockIdx.x == 0 && blockIdx.y == 0) {
        for (int i = tid; i < NBANK * 64; i += 256) {
            g_sum[i] = 0.f;
            g_sq[i]  = 0.f;
        }
    }
}

// ---------------------------------------------------------------- launch
extern "C" void kernel_launch(void* const* d_in, const int* in_sizes, int n_in,
                              void* d_out, int out_size)
{
    (void)in_sizes; (void)n_in; (void)out_size;
    const float* x     = (const float*)d_in[0];
    const float* Wq    = (const float*)d_in[1];
    const float* bq    = (const float*)d_in[2];
    const float* gq    = (const float*)d_in[3];
    const float* betaq = (const float*)d_in[4];
    const float* Wk    = (const float*)d_in[5];
    const float* bk    = (const float*)d_in[6];
    const float* gk    = (const float*)d_in[7];
    const float* betak = (const float*)d_in[8];
    const float* Wv    = (const float*)d_in[9];
    const float* bv    = (const float*)d_in[10];
    float* out = (float*)d_out;

    cudaFuncSetAttribute(attn_kernel, cudaFuncAttributeMaxDynamicSharedMemorySize,
                         SMEM_BYTES);

    conv_kernel<<<1024, 256>>>(x, Wq, bq, Wk, bk, Wv, bv);
    bn_kernel<<<1, 64>>>(gq, betaq, gk, betak);
    prep_kernel<<<4096, 256>>>();
    attn_kernel<<<dim3(16, 16), 256, SMEM_BYTES>>>(out);
}

// round 14
// speedup vs baseline: 1.2430x; 1.0037x over previous
#include <cuda_runtime.h>
#include <cuda_fp16.h>
#include <math.h>
#include <cstdint>

// ---------------------------------------------------------------- constants
#define NBLK  16
#define LSEQ  2048
#define CKD   32
#define CVD   64
#define NPOSF 32768.0f
#define EPSB  1e-5f
#define SCALE_Q 0.25505654350925196f   // (1/sqrt(32)) * log2(e)
#define NBANK 32

// per-(nb,kt) staged tile blob: [K fp16 10240 | V fp16 17408]
#define TILE_BYTES 27648
#define BLOB_V     10240

// ---------------------------------------------------------------- scratch
__device__ float g_q [NBLK * LSEQ * CKD];
__device__ float g_k [NBLK * LSEQ * CKD];
__device__ __half g_qh[NBLK * LSEQ * CKD];
__device__ __align__(128) unsigned char g_tiles[NBLK * 16 * TILE_BYTES];
__device__ float g_sum[NBANK * 64], g_sq[NBANK * 64];  // zero at load; attn re-zeroes
__device__ float g_affa[64], g_affc[64];

// ---------------------------------------------------------------- helpers
__device__ __forceinline__ void mma_f16(float* c, const uint32_t* a,
                                        uint32_t b0, uint32_t b1) {
    asm volatile(
        "mma.sync.aligned.m16n8k16.row.col.f32.f16.f16.f32 "
        "{%0,%1,%2,%3}, {%4,%5,%6,%7}, {%8,%9}, {%0,%1,%2,%3};"
        : "+f"(c[0]), "+f"(c[1]), "+f"(c[2]), "+f"(c[3])
        : "r"(a[0]), "r"(a[1]), "r"(a[2]), "r"(a[3]), "r"(b0), "r"(b1));
}
__device__ __forceinline__ uint32_t pack_f16x2(float lo, float hi) {
    uint32_t r;
    asm("cvt.rn.f16x2.f32 %0, %1, %2;" : "=r"(r) : "f"(hi), "f"(lo));
    return r;
}
// single-instruction MUFU.EX2 (exp2f without fast-math is a slow software path)
__device__ __forceinline__ float ex2(float x) {
    float r;
    asm("ex2.approx.ftz.f32 %0, %1;" : "=f"(r) : "f"(x));
    return r;
}
#define LDSM_X4(r0, r1, r2, r3, addr) \
    asm volatile("ldmatrix.sync.aligned.m8n8.x4.shared.b16 {%0,%1,%2,%3}, [%4];" \
        : "=r"(r0), "=r"(r1), "=r"(r2), "=r"(r3) : "r"(addr))

#define MBARRIER_INIT(mb, cnt) \
    asm volatile("mbarrier.init.shared.b64 [%0], %1;" :: "r"((uint32_t)(mb)), "r"((uint32_t)(cnt)) : "memory")
#define MBARRIER_EXPECT_TX(mb, bytes) \
    asm volatile("mbarrier.arrive.expect_tx.shared.b64 _, [%0], %1;" :: "r"((uint32_t)(mb)), "r"((uint32_t)(bytes)) : "memory")
#define CP_BULK(dst, src, bytes, mbar) \
    asm volatile("cp.async.bulk.shared::cta.global.mbarrier::complete_tx::bytes [%0], [%1], %2, [%3];" \
                 :: "r"((uint32_t)(dst)), "l"(src), "r"((uint32_t)(bytes)), "r"((uint32_t)(mbar)) : "memory")
#define MBARRIER_WAIT_PARITY(mb, par) do {                                          \
    uint32_t _mbar = (uint32_t)(mb); uint32_t _par = (uint32_t)(par); uint32_t _done;\
    asm volatile("{\n\t.reg .pred p;\n\t"                                           \
        "mbarrier.try_wait.parity.acquire.cta.shared::cta.b64 p, [%1], %2;\n\t"     \
        "selp.b32 %0, 1, 0, p;\n\t}" : "=r"(_done) : "r"(_mbar), "r"(_par) : "memory"); \
    if (!_done) {                                                                   \
        asm volatile("{\n\t.reg .pred P1;\n\t"                                      \
            "WAIT_LOOP_%=:\n\t"                                                     \
            "mbarrier.try_wait.parity.acquire.cta.shared::cta.b64 P1, [%0], %1, 0x989680;\n\t" \
            "@P1 bra.uni WAIT_DONE_%=;\n\t"                                         \
            "bra.uni WAIT_LOOP_%=;\n\t"                                             \
            "WAIT_DONE_%=:\n\t}" :: "r"(_mbar), "r"(_par) : "memory");              \
    } } while (0)

__device__ __forceinline__ uint32_t smem_u32(const void* p) {
    uint32_t a;
    asm("{ .reg .u64 t; cvta.to.shared.u64 t, %1; cvt.u32.u64 %0, t; }" : "=r"(a) : "l"(p));
    return a;
}

// ---------------------------------------------------------------- kernel 1: conv1x1
// CTA = (n, h, w0): 16 w-positions x 2 sides = 32 consecutive l per (nb,kt).
// 256 threads = 128 oc x 2 pixel-halves (ph): thread owns 8 w-positions x 2 sides.
__global__ __launch_bounds__(256) void conv_kernel(
    const float* __restrict__ x,
    const float* __restrict__ Wq, const float* __restrict__ bq,
    const float* __restrict__ Wk, const float* __restrict__ bk,
    const float* __restrict__ Wv, const float* __restrict__ bv)
{
    __shared__ float xs[64 * 32];
    __shared__ float wsm[128 * 65];
    const int tid = threadIdx.x;
    const int bid = blockIdx.x;
    const int n   = bid >> 8;
    const int rem = bid & 255;
    const int h   = rem >> 2;
    const int w0  = (rem & 3) * 16;

    const float* xbase = x + (size_t)n * 64 * 8192 + h * 128;
    for (int f = tid; f < 64 * 32; f += 256) {
        int c = f >> 5, pos = f & 31;
        int w2 = ((pos >> 4) << 6) + w0 + (pos & 15);
        xs[c * 32 + pos] = xbase[c * 8192 + w2];
    }
    for (int f = tid; f < 128 * 64; f += 256) {
        int o = f >> 6, c = f & 63;
        float w;
        if      (o < 32) w = Wq[o * 64 + c];
        else if (o < 64) w = Wk[(o - 32) * 64 + c];
        else             w = Wv[(o - 64) * 64 + c];
        wsm[o * 65 + c] = w;
    }
    __syncthreads();

    const int oc = tid & 127;
    const int ph = tid >> 7;      // pixel half: w-positions [ph*8, ph*8+8)
    float bias;
    if      (oc < 32) bias = bq[oc];
    else if (oc < 64) bias = bk[oc - 32];
    else              bias = bv[oc - 64];

    // acc[s*8 + j]: side s, w-position ph*8+j
    float acc[16];
#pragma unroll
    for (int p = 0; p < 16; p++) acc[p] = bias;

    const float4* xs4 = (const float4*)xs;
#pragma unroll 8
    for (int c = 0; c < 64; c++) {
        float wv = wsm[oc * 65 + c];
#pragma unroll
        for (int s = 0; s < 2; s++) {
            float4 xa = xs4[c * 8 + s * 4 + ph * 2];
            float4 xb = xs4[c * 8 + s * 4 + ph * 2 + 1];
            acc[s * 8 + 0] += wv * xa.x;
            acc[s * 8 + 1] += wv * xa.y;
            acc[s * 8 + 2] += wv * xa.z;
            acc[s * 8 + 3] += wv * xa.w;
            acc[s * 8 + 4] += wv * xb.x;
            acc[s * 8 + 5] += wv * xb.y;
            acc[s * 8 + 6] += wv * xb.z;
            acc[s * 8 + 7] += wv * xb.w;
        }
    }

    const int b    = ((h >> 5) << 1) | (w0 >> 5);
    const int nb   = (n << 2) | b;
    const int l0   = ((h & 31) * 32 + (w0 & 31)) * 2;   // base l for this CTA
    const int kt   = l0 >> 7;
    const int key0 = l0 & 127;

    if (oc < 64) {
        float s = 0.f, sq = 0.f;
#pragma unroll
        for (int p = 0; p < 16; p++) {
            int side = p >> 3, j = p & 7;
            int l = l0 + ((ph * 8 + j) << 1) + side;
            float v = acc[p];
            if (oc < 32) g_q[(size_t)(nb * LSEQ + l) * CKD + oc]        = v;
            else         g_k[(size_t)(nb * LSEQ + l) * CKD + (oc - 32)] = v;
            s += v; sq += v * v;
        }
        const int bank = (bid & (NBANK - 1)) * 64 + oc;
        atomicAdd(&g_sum[bank], s);
        atomicAdd(&g_sq[bank],  sq);
    } else {
        // V: fp16, straight into the tile blob (contiguous 32B per thread)
        const int cv = oc - 64;
        uint32_t pk[8];
#pragma unroll
        for (int j = 0; j < 8; j++) pk[j] = pack_f16x2(acc[j], acc[8 + j]);
        unsigned char* dst = g_tiles + (size_t)(nb * 16 + kt) * TILE_BYTES
                             + BLOB_V + cv * 272 + (key0 + ph * 16) * 2;
        *(uint4*)(dst)      = make_uint4(pk[0], pk[1], pk[2], pk[3]);
        *(uint4*)(dst + 16) = make_uint4(pk[4], pk[5], pk[6], pk[7]);
    }
}

// ---------------------------------------------------------------- kernel 2: BN fold (banked reduce)
__global__ void bn_kernel(const float* __restrict__ gq, const float* __restrict__ betaq,
                          const float* __restrict__ gk, const float* __restrict__ betak)
{
    int c = threadIdx.x;  // 0..63
    float s = 0.f, sq = 0.f;
#pragma unroll
    for (int b = 0; b < NBANK; b++) {
        s  += g_sum[b * 64 + c];
        sq += g_sq [b * 64 + c];
    }
    float mean = s / NPOSF;
    float var  = sq / NPOSF - mean * mean;
    float gg   = (c < 32) ? gq[c]    : gk[c - 32];
    float be   = (c < 32) ? betaq[c] : betak[c - 32];
    float a    = gg * rsqrtf(var + EPSB);
    g_affa[c] = a;
    g_affc[c] = be - mean * a;
}

// ---------------------------------------------------------------- kernel 3: prep (q/k only, fp16)
__global__ __launch_bounds__(256) void prep_kernel() {
    int idx = blockIdx.x * 256 + threadIdx.x;       // 0 .. 1M-1 (pairs)
    int which = idx >> 19;                          // 0: q, 1: k
    int i = (idx & 524287) * 2;
    int ck = i & 31;
    const float* src = which ? g_k : g_q;
    float2 rv = *(const float2*)(src + i);
    int base = which ? 32 : 0;
    float a0 = g_affa[base + ck],     c0 = g_affc[base + ck];
    float a1 = g_affa[base + ck + 1], c1 = g_affc[base + ck + 1];
    float y0 = rv.x * a0 + c0;
    float y1 = rv.y * a1 + c1;
    if (!which) { y0 *= SCALE_Q; y1 *= SCALE_Q; }
    uint32_t hw = pack_f16x2(y0, y1);
    if (which) {
        int nb  = i >> 16;
        int rem = i & 65535;
        int l   = rem >> 5;
        int kt  = l >> 7, row = l & 127;
        *(uint32_t*)(g_tiles + (size_t)(nb * 16 + kt) * TILE_BYTES + row * 80 + ck * 2) = hw;
    } else {
        ((uint32_t*)g_qh)[i >> 1] = hw;
    }
}

// ---------------------------------------------------------------- attention
// 256 threads, 8 warps; warp w owns rows w*16..w*16+15, all 128 keys.
// smem byte layout:
//  buf b (b=0,1) at b*27648: K fp16 +0 (pitch 80) | V fp16 +10240 (pitch 272)
//  Q:   55296 (fp16, pitch 80, 10240 B)
//  mbar:65536 (2 x 8B)
#define OFF_Q    55296
#define OFF_MBAR 65536
#define SMEM_BYTES 65792
#define STG_PITCH 66       // float staging overlays offset 0 at the end

extern __shared__ char s_raw[];

__global__ __launch_bounds__(256, 2) void attn_kernel(float* __restrict__ out)
{
    const uint32_t sb = smem_u32(s_raw);
    float* stg = (float*)s_raw;

    const int tid = threadIdx.x;
    const int w   = tid >> 5;      // warp = m band: rows w*16 .. +15
    const int ln  = tid & 31;
    const int qr  = ln >> 2;
    const int qc  = ln & 3;
    const int nb    = blockIdx.y;
    const int chunk = blockIdx.x;
    const int qbase = chunk * 128;

    const int li   = ln & 7;
    const int tsel = ln >> 3;

    const uint32_t kbase = (uint32_t)(((tsel >> 1) * 8 + li) * 80 + (tsel & 1) * 16);
    const uint32_t vbase = (uint32_t)(((tsel >> 1) * 8 + li) * 272 + ((tsel & 1) * 8) * 2);
    const uint32_t qfrag = (uint32_t)((w * 16 + (tsel & 1) * 8 + li) * 80 + (tsel >> 1) * 16);

    const unsigned char* tiles = g_tiles + (size_t)nb * 16 * TILE_BYTES;

    // ---- init mbarriers, kick tile-0 bulk copy, stage Q ----
    if (tid == 0) {
        MBARRIER_INIT(sb + OFF_MBAR,     1);
        MBARRIER_INIT(sb + OFF_MBAR + 8, 1);
    }
    __syncthreads();
    if (tid == 0) {
        MBARRIER_EXPECT_TX(sb + OFF_MBAR, TILE_BYTES);
        CP_BULK(sb, tiles, TILE_BYTES, sb + OFF_MBAR);
    }
    for (int f = tid; f < 512; f += 256) {
        int row = f >> 2, j = f & 3;
        const size_t src = ((size_t)(nb * LSEQ + qbase + row)) * CKD + j * 8;
        *(uint4*)(s_raw + OFF_Q + row * 80 + j * 16) = *(const uint4*)(g_qh + src);
    }
    __syncthreads();

    // ---- hoist Q fragments ----
    uint32_t Qh[2][4];
#pragma unroll
    for (int s = 0; s < 2; s++)
        LDSM_X4(Qh[s][0], Qh[s][1], Qh[s][2], Qh[s][3], sb + OFF_Q + s * 32 + qfrag);

    float O[8][4];
#pragma unroll
    for (int v = 0; v < 8; v++)
#pragma unroll
        for (int j = 0; j < 4; j++) O[v][j] = 0.f;
    float rs0 = 0.f, rs1 = 0.f;

    for (int kt = 0; kt < 16; kt++) {
        MBARRIER_WAIT_PARITY(sb + OFF_MBAR + (kt & 1) * 8, (kt >> 1) & 1);
        __syncthreads();
        if (tid == 0 && kt < 15) {
            const uint32_t mbn = sb + OFF_MBAR + ((kt + 1) & 1) * 8;
            MBARRIER_EXPECT_TX(mbn, TILE_BYTES);
            CP_BULK(sb + ((kt + 1) & 1) * TILE_BYTES,
                    tiles + (size_t)(kt + 1) * TILE_BYTES, TILE_BYTES, mbn);
        }

        const uint32_t kB = sb + (kt & 1) * TILE_BYTES;
        const uint32_t vB = kB + BLOB_V;

        // ---- fused per key-pair (16 keys): S mma -> ex2 -> fp16 pack -> PV mma ----
#pragma unroll
        for (int t = 0; t < 8; t++) {
            float P0[4] = {0.f, 0.f, 0.f, 0.f};
            float P1[4] = {0.f, 0.f, 0.f, 0.f};
#pragma unroll
            for (int s = 0; s < 2; s++) {
                uint32_t kh[4];
                LDSM_X4(kh[0], kh[1], kh[2], kh[3], kB + t * 1280 + s * 32 + kbase);
                mma_f16(P0, Qh[s], kh[0], kh[1]);
                mma_f16(P1, Qh[s], kh[2], kh[3]);
            }

#pragma unroll
            for (int j = 0; j < 4; j++) { P0[j] = ex2(P0[j]); P1[j] = ex2(P1[j]); }
            rs0 += P0[0] + P0[1] + P1[0] + P1[1];
            rs1 += P0[2] + P0[3] + P1[2] + P1[3];

            uint32_t A[4];
            A[0] = pack_f16x2(P0[0], P0[1]);
            A[1] = pack_f16x2(P0[2], P0[3]);
            A[2] = pack_f16x2(P1[0], P1[1]);
            A[3] = pack_f16x2(P1[2], P1[3]);

#pragma unroll
            for (int i = 0; i < 4; i++) {
                const int vp = 2 * i;
                uint32_t vh[4];
                LDSM_X4(vh[0], vh[1], vh[2], vh[3], vB + vp * 2176 + t * 32 + vbase);
                mma_f16(O[vp],     A, vh[0], vh[1]);
                mma_f16(O[vp + 1], A, vh[2], vh[3]);
            }
        }
    }

    // ---- normalize in-register, stage, scatter ----
    rs0 += __shfl_xor_sync(0xffffffffu, rs0, 1);
    rs0 += __shfl_xor_sync(0xffffffffu, rs0, 2);
    rs1 += __shfl_xor_sync(0xffffffffu, rs1, 1);
    rs1 += __shfl_xor_sync(0xffffffffu, rs1, 2);
    const float inv0 = 1.0f / rs0;
    const float inv1 = 1.0f / rs1;
    const int row0 = w * 16 + qr;

    __syncthreads();   // all smem-tile reads done; stg overlay safe
#pragma unroll
    for (int v = 0; v < 8; v++) {
        int cv = v * 8 + qc * 2;
        *(float2*)&stg[(row0)     * STG_PITCH + cv] =
            make_float2(O[v][0] * inv0, O[v][1] * inv0);
        *(float2*)&stg[(row0 + 8) * STG_PITCH + cv] =
            make_float2(O[v][2] * inv1, O[v][3] * inv1);
    }
    __syncthreads();

    const int n = nb >> 2, b = nb & 3;
    const int bi = b >> 1, bj = b & 1;
    for (int e = tid; e < 8192; e += 256) {
        int wl   = e & 31;
        int side = (e >> 5) & 1;
        int hlo  = (e >> 6) & 1;
        int cv   = e >> 7;
        int ll   = hlo * 64 + wl * 2 + side;
        int hh   = bi * 32 + chunk * 2 + hlo;
        int w2   = side * 64 + bj * 32 + wl;
        out[(((size_t)(n * 64 + cv)) * 64 + hh) * 128 + w2] = stg[ll * STG_PITCH + cv];
    }

    // re-zero banked BN stat accumulators for the next launch
    if (blockIdx.x == 0 && blockIdx.y == 0) {
        for (int i = tid; i < NBANK * 64; i += 256) {
            g_sum[i] = 0.f;
            g_sq[i]  = 0.f;
        }
    }
}

// ---------------------------------------------------------------- launch
extern "C" void kernel_launch(void* const* d_in, const int* in_sizes, int n_in,
                              void* d_out, int out_size)
{
    (void)in_sizes; (void)n_in; (void)out_size;
    const float* x     = (const float*)d_in[0];
    const float* Wq    = (const float*)d_in[1];
    const float* bq    = (const float*)d_in[2];
    const float* gq    = (const float*)d_in[3];
    const float* betaq = (const float*)d_in[4];
    const float* gk    = (const float*)d_in[7];
    const float* bk    = (const float*)d_in[6];
    const float* Wk    = (const float*)d_in[5];
    const float* betak = (const float*)d_in[8];
    const float* Wv    = (const float*)d_in[9];
    const float* bv    = (const float*)d_in[10];
    float* out = (float*)d_out;

    cudaFuncSetAttribute(attn_kernel, cudaFuncAttributeMaxDynamicSharedMemorySize,
                         SMEM_BYTES);

    conv_kernel<<<1024, 256>>>(x, Wq, bq, Wk, bk, Wv, bv);
    bn_kernel<<<1, 64>>>(gq, betaq, gk, betak);
    prep_kernel<<<4096, 256>>>();
    attn_kernel<<<dim3(16, 16), 256, SMEM_BYTES>>>(out);
}